// round 5
// baseline (speedup 1.0000x reference)
#include <cuda_runtime.h>

// CapsuleBlock: B=64, N=2048, D_in=8, K=16, O=16, 3 routing iters.
// R5: no hats materialization (killed the 67MB write + 2x67MB read wall).
// 3 FMA-bound compute passes. Thread = (b, o-quad): softmax over k is
// thread-local; bias combine = 2 intra-warp shuffles. route read from
// L1-resident g_route. All fp32. Profiler lands on 4th launch = pass2.

#define NBLK  148
#define CHUNK 14           // 148*14 = 2072 >= 2048

__device__ float g_part[(size_t)NBLK * 16384];   // partials [blk][b][k][o]
__device__ float g_route[16384];                 // routing vector [b][k][o]

typedef unsigned long long ull;

__device__ __forceinline__ ull pack2(float v) {
    ull r; asm("mov.b64 %0, {%1, %1};" : "=l"(r) : "f"(v)); return r;
}
__device__ __forceinline__ ull fma2(ull a, ull b, ull c) {
    ull d; asm("fma.rn.f32x2 %0, %1, %2, %3;" : "=l"(d) : "l"(a), "l"(b), "l"(c)); return d;
}
__device__ __forceinline__ ull mul2(ull a, ull b) {
    ull d; asm("mul.rn.f32x2 %0, %1, %2;" : "=l"(d) : "l"(a), "l"(b)); return d;
}
__device__ __forceinline__ ull add2(ull a, ull b) {
    ull d; asm("add.rn.f32x2 %0, %1, %2;" : "=l"(d) : "l"(a), "l"(b)); return d;
}
__device__ __forceinline__ float2 unpack2(ull v) {
    float2 r; asm("mov.b64 {%0, %1}, %2;" : "=f"(r.x), "=f"(r.y) : "l"(v)); return r;
}

__global__ void noop_kernel() {}

// pass: per n, h[b,k,o] = sum_d x[b,n,d] W[n,k,d,o].
// FIRST: acc += h (uniform c folded into squash scale).
// else:  bias_k = <h, route>, softmax over k, acc += c_k * h.
// thread = (b, oq): b = tid>>2 (64), oq = tid&3 (o-quad).
template <bool FIRST>
__global__ void __launch_bounds__(256, 1)
pass_kernel(const float* __restrict__ x, const float* __restrict__ W) {
    __shared__ __align__(16) float Ws[8][16][16];     // [d][k][o], 8 KB
    __shared__ float xs[CHUNK][8][64];                // [ln][d][b], 28 KB

    const int tid = threadIdx.x;
    const int b  = tid >> 2;
    const int oq = tid & 3;
    const int n0 = blockIdx.x * CHUNK;
    int nmax = 2048 - n0; if (nmax > CHUNK) nmax = CHUNK; if (nmax < 0) nmax = 0;

    // ---- stage x[:, n0:n0+nmax, :] as [ln][d][b] ----
    for (int i = tid; i < nmax * 128; i += 256) {
        int ln = i >> 7, r = i & 127, bb = r >> 1, dq = r & 1;
        float4 v = *(const float4*)(x + ((size_t)bb * 2048 + (size_t)(n0 + ln)) * 8 + dq * 4);
        xs[ln][dq * 4 + 0][bb] = v.x;
        xs[ln][dq * 4 + 1][bb] = v.y;
        xs[ln][dq * 4 + 2][bb] = v.z;
        xs[ln][dq * 4 + 3][bb] = v.w;
    }

    // ---- W staging: thread t covers floats [t*8, t*8+8) of W[n] (k,d,o) ----
    const int kw = tid >> 4, dw = (tid >> 1) & 7, ow = (tid & 1) * 8;
    const size_t woff = (size_t)tid * 8;
    float4 w0 = make_float4(0.f, 0.f, 0.f, 0.f), w1 = w0;
    if (nmax > 0) {
        w0 = *(const float4*)(W + (size_t)n0 * 2048 + woff);
        w1 = *(const float4*)(W + (size_t)n0 * 2048 + woff + 4);
    }

    ull acc[16][2];
#pragma unroll
    for (int k = 0; k < 16; k++) { acc[k][0] = 0ull; acc[k][1] = 0ull; }

    const float* rp = g_route + (size_t)b * 256 + (size_t)oq * 4;  // [k*16] stride

    for (int ln = 0; ln < nmax; ln++) {
        *(float4*)&Ws[dw][kw][ow]     = w0;
        *(float4*)&Ws[dw][kw][ow + 4] = w1;
        __syncthreads();
        if (ln + 1 < nmax) {
            w0 = *(const float4*)(W + (size_t)(n0 + ln + 1) * 2048 + woff);
            w1 = *(const float4*)(W + (size_t)(n0 + ln + 1) * 2048 + woff + 4);
        }

        // h[k][2] : this thread's (b, k, oq*4..+3) slice
        ull h[16][2];
#pragma unroll
        for (int d = 0; d < 8; d++) {
            ull xb = pack2(xs[ln][d][b]);
#pragma unroll
            for (int k = 0; k < 16; k++) {
                ulonglong2 wv = *(const ulonglong2*)&Ws[d][k][oq * 4];
                if (d == 0) {
                    h[k][0] = mul2(xb, wv.x);
                    h[k][1] = mul2(xb, wv.y);
                } else {
                    h[k][0] = fma2(xb, wv.x, h[k][0]);
                    h[k][1] = fma2(xb, wv.y, h[k][1]);
                }
            }
        }
        __syncthreads();   // Ws reads done before next store

        if (FIRST) {
#pragma unroll
            for (int k = 0; k < 16; k++) {
                acc[k][0] = add2(acc[k][0], h[k][0]);
                acc[k][1] = add2(acc[k][1], h[k][1]);
            }
        } else {
            // bias_k = sum_o h * route  (partial over this thread's 4 o,
            // completed across the 4 oq threads via xor-1,2 shuffles)
            float bias[16];
#pragma unroll
            for (int k = 0; k < 16; k++) {
                ulonglong2 rv = *(const ulonglong2*)(rp + (size_t)k * 16);
                ull t = mul2(h[k][0], rv.x);
                t = fma2(h[k][1], rv.y, t);
                float2 q = unpack2(t);
                float pb = q.x + q.y;
                pb += __shfl_xor_sync(0xffffffffu, pb, 1);
                pb += __shfl_xor_sync(0xffffffffu, pb, 2);
                bias[k] = pb;
            }
            // softmax over k — fully thread-local
            float m01 = fmaxf(bias[0], bias[1]);
            float m23 = fmaxf(bias[2], bias[3]);
            float m45 = fmaxf(bias[4], bias[5]);
            float m67 = fmaxf(bias[6], bias[7]);
            float m89 = fmaxf(bias[8], bias[9]);
            float mab = fmaxf(bias[10], bias[11]);
            float mcd = fmaxf(bias[12], bias[13]);
            float mef = fmaxf(bias[14], bias[15]);
            float m0 = fmaxf(fmaxf(m01, m23), fmaxf(m45, m67));
            float m1 = fmaxf(fmaxf(m89, mab), fmaxf(mcd, mef));
            float m  = fmaxf(m0, m1);
            float e[16], s = 0.f;
#pragma unroll
            for (int k = 0; k < 16; k++) { e[k] = __expf(bias[k] - m); s += e[k]; }
            float inv = __fdividef(1.0f, s);
#pragma unroll
            for (int k = 0; k < 16; k++) {
                ull c2 = pack2(e[k] * inv);
                acc[k][0] = fma2(c2, h[k][0], acc[k][0]);
                acc[k][1] = fma2(c2, h[k][1], acc[k][1]);
            }
        }
    }

    // ---- write partials [blk][b][k][o] ----
    float* pp = g_part + ((size_t)blockIdx.x * 64 + b) * 256 + (size_t)oq * 4;
#pragma unroll
    for (int k = 0; k < 16; k++) {
        float2 v0 = unpack2(acc[k][0]);
        float2 v1 = unpack2(acc[k][1]);
        *(float4*)(pp + (size_t)k * 16) = make_float4(v0.x, v0.y, v1.x, v1.y);
    }
}

// Reduce NBLK partials, squash, update route / emit output.
// grid 64 (b), block 1024: q = tid>>8 (4-way n-split), t = tid&255 = k*16+o.
__global__ void __launch_bounds__(1024) squash_kernel(float scale, int mode,
                                                      float* __restrict__ out) {
    __shared__ float red[4][256];
    const int tid = threadIdx.x, q = tid >> 8, t = tid & 255;
    const int b = blockIdx.x;
    float s = 0.f;
#pragma unroll 4
    for (int j = q; j < NBLK; j += 4)
        s += g_part[((size_t)j * 64 + b) * 256 + t];
    red[q][t] = s;
    __syncthreads();
    if (tid < 256) {
        s = (red[0][t] + red[1][t]) + (red[2][t] + red[3][t]);
        s *= scale;
        float s2 = s * s;
        s2 += __shfl_xor_sync(0xffffffffu, s2, 1);
        s2 += __shfl_xor_sync(0xffffffffu, s2, 2);
        s2 += __shfl_xor_sync(0xffffffffu, s2, 4);
        s2 += __shfl_xor_sync(0xffffffffu, s2, 8);
        float sc = s2 / ((1.0f + s2) * sqrtf(s2));
        float v = sc * s;
        int idx = b * 256 + t;
        if (mode == 0)      g_route[idx] = v;    // route = out0
        else if (mode == 1) g_route[idx] += v;   // route = out0 + out1
        else                out[idx] = v;        // final [B,16,16]
    }
}

extern "C" void kernel_launch(void* const* d_in, const int* in_sizes, int n_in,
                              void* d_out, int out_size) {
    const float* x = (const float*)d_in[0];   // [64, 2048, 8]
    const float* W = (const float*)d_in[1];   // [2048, 16, 8, 16]
    float* out = (float*)d_out;               // [64, 16, 16]
    (void)in_sizes; (void)n_in; (void)out_size;

    noop_kernel<<<1, 1>>>();                              // aligns profiler on pass2
    pass_kernel<true ><<<NBLK, 256>>>(x, W);              // s0 partials
    squash_kernel<<<64, 1024>>>(1.0f / 16.0f, 0, out);    // out0 -> route
    pass_kernel<false><<<NBLK, 256>>>(x, W);              // 4th launch (profiled)
    squash_kernel<<<64, 1024>>>(1.0f, 1, out);            // route += out1
    pass_kernel<false><<<NBLK, 256>>>(x, W);              // s2 partials
    squash_kernel<<<64, 1024>>>(1.0f, 2, out);            // final output
}

// round 6
// speedup vs baseline: 1.0325x; 1.0325x over previous
#include <cuda_runtime.h>

// CapsuleBlock: B=64, N=2048, D_in=8, K=16, O=16, 3 routing iters.
// R6: thread = (k-pair, b). 512-thr blocks, 16 warps/SM (was 8), ~120 regs
// (was 252). W smem layout [d][kk][oq][kp pad 9] -> every compute LDS.128 is
// one conflict-free phase. Softmax: 2 thread-local biases + 6 shuffles/n.
// All fp32. Profiler lands on 4th launch = pass<false>.

#define NBLK  148
#define CHUNK 14           // 148*14 = 2072 >= 2048

__device__ float g_part[(size_t)NBLK * 16384];   // partials [blk][b][k][o]
__device__ float g_route[16384];                 // routing vector [b][k][o]

typedef unsigned long long ull;

__device__ __forceinline__ ull pack2(float v) {
    ull r; asm("mov.b64 %0, {%1, %1};" : "=l"(r) : "f"(v)); return r;
}
__device__ __forceinline__ ull fma2(ull a, ull b, ull c) {
    ull d; asm("fma.rn.f32x2 %0, %1, %2, %3;" : "=l"(d) : "l"(a), "l"(b), "l"(c)); return d;
}
__device__ __forceinline__ ull mul2(ull a, ull b) {
    ull d; asm("mul.rn.f32x2 %0, %1, %2;" : "=l"(d) : "l"(a), "l"(b)); return d;
}
__device__ __forceinline__ ull add2(ull a, ull b) {
    ull d; asm("add.rn.f32x2 %0, %1, %2;" : "=l"(d) : "l"(a), "l"(b)); return d;
}
__device__ __forceinline__ float2 unpack2(ull v) {
    float2 r; asm("mov.b64 {%0, %1}, %2;" : "=f"(r.x), "=f"(r.y) : "l"(v)); return r;
}

__global__ void noop_kernel() {}

// pass: per n, h[b,k,o] = sum_d x[b,n,d] W[n,k,d,o].
// FIRST: acc += h. else: bias_k = <h,route>, softmax over k, acc += c_k h.
// Block 512 thr: warp w covers b = 4w + (l>>3); lane kp = l&7 owns k = 2kp, 2kp+1.
template <bool FIRST>
__global__ void __launch_bounds__(512, 1)
pass_kernel(const float* __restrict__ x, const float* __restrict__ W) {
    // W layout: float4 units, index (((d*2+kk)*4+oq)*9 + kp); pad 9 => the 8 kp
    // lanes' 16B chunks land on 8 distinct bank groups (conflict-free).
    __shared__ __align__(16) float4 Wsf4[8 * 2 * 4 * 9];   // 9216 B
    __shared__ __align__(16) float xs[CHUNK][64][8];       // 28 KB

    const int tid = threadIdx.x;
    const int l   = tid & 31;
    const int kp  = l & 7;
    const int b   = (tid >> 5) * 4 + (l >> 3);
    const int n0  = blockIdx.x * CHUNK;
    int nmax = 2048 - n0; if (nmax > CHUNK) nmax = CHUNK; if (nmax < 0) nmax = 0;

    // ---- stage x chunk: xs[ln][b][d] ----
    for (int i = tid; i < nmax * 128; i += 512) {
        int ln = i >> 7, r = i & 127, bb = r >> 1, dq = r & 1;
        float4 v = *(const float4*)(x + ((size_t)bb * 2048 + (size_t)(n0 + ln)) * 8 + dq * 4);
        *(float4*)&xs[ln][bb][dq * 4] = v;
    }

    // ---- W staging map: thread t stages gmem float4 #t of W[n] row ----
    const int kW = tid >> 5, dW = (tid >> 2) & 7, oqW = tid & 3;
    const int wdst = ((dW * 2 + (kW & 1)) * 4 + oqW) * 9 + (kW >> 1);
    const float4* wsrc = (const float4*)(W + (size_t)n0 * 2048) + tid;
    float4 wreg = make_float4(0.f, 0.f, 0.f, 0.f);
    if (nmax > 0) wreg = wsrc[0];

    ull acc[2][8];
#pragma unroll
    for (int kk = 0; kk < 2; kk++)
#pragma unroll
        for (int j = 0; j < 8; j++) acc[kk][j] = 0ull;

    ull rr[2][8];
    if (!FIRST) {
#pragma unroll
        for (int kk = 0; kk < 2; kk++) {
            const ull* rp = (const ull*)(g_route + (size_t)b * 256 + (size_t)(2 * kp + kk) * 16);
#pragma unroll
            for (int j = 0; j < 8; j++) rr[kk][j] = rp[j];
        }
    }

    for (int ln = 0; ln < nmax; ln++) {
        Wsf4[wdst] = wreg;
        __syncthreads();
        if (ln + 1 < nmax) wreg = wsrc[(size_t)(ln + 1) * 512];

        float x8[8];
        *(float4*)&x8[0] = *(const float4*)&xs[ln][b][0];
        *(float4*)&x8[4] = *(const float4*)&xs[ln][b][4];

        ull h[2][8];
#pragma unroll
        for (int d = 0; d < 8; d++) {
            ull xd = pack2(x8[d]);
#pragma unroll
            for (int kk = 0; kk < 2; kk++) {
#pragma unroll
                for (int oq = 0; oq < 4; oq++) {
                    ulonglong2 wv = *(const ulonglong2*)&Wsf4[((d * 2 + kk) * 4 + oq) * 9 + kp];
                    if (FIRST) {
                        acc[kk][2 * oq]     = fma2(xd, wv.x, acc[kk][2 * oq]);
                        acc[kk][2 * oq + 1] = fma2(xd, wv.y, acc[kk][2 * oq + 1]);
                    } else if (d == 0) {
                        h[kk][2 * oq]     = mul2(xd, wv.x);
                        h[kk][2 * oq + 1] = mul2(xd, wv.y);
                    } else {
                        h[kk][2 * oq]     = fma2(xd, wv.x, h[kk][2 * oq]);
                        h[kk][2 * oq + 1] = fma2(xd, wv.y, h[kk][2 * oq + 1]);
                    }
                }
            }
        }
        __syncthreads();   // Ws reads done before next staging store

        if (!FIRST) {
            // thread-local biases for k = 2kp, 2kp+1
            ull t0 = mul2(h[0][0], rr[0][0]);
            ull t1 = mul2(h[1][0], rr[1][0]);
#pragma unroll
            for (int j = 1; j < 8; j++) {
                t0 = fma2(h[0][j], rr[0][j], t0);
                t1 = fma2(h[1][j], rr[1][j], t1);
            }
            float2 q0 = unpack2(t0), q1 = unpack2(t1);
            float bias0 = q0.x + q0.y;
            float bias1 = q1.x + q1.y;
            // softmax over 16 k: local pair + xor 1,2,4 within the 8 kp lanes
            float m = fmaxf(bias0, bias1);
            m = fmaxf(m, __shfl_xor_sync(0xffffffffu, m, 1));
            m = fmaxf(m, __shfl_xor_sync(0xffffffffu, m, 2));
            m = fmaxf(m, __shfl_xor_sync(0xffffffffu, m, 4));
            float e0 = __expf(bias0 - m), e1 = __expf(bias1 - m);
            float s = e0 + e1;
            s += __shfl_xor_sync(0xffffffffu, s, 1);
            s += __shfl_xor_sync(0xffffffffu, s, 2);
            s += __shfl_xor_sync(0xffffffffu, s, 4);
            float inv = __fdividef(1.0f, s);
            ull c0 = pack2(e0 * inv), c1 = pack2(e1 * inv);
#pragma unroll
            for (int j = 0; j < 8; j++) {
                acc[0][j] = fma2(c0, h[0][j], acc[0][j]);
                acc[1][j] = fma2(c1, h[1][j], acc[1][j]);
            }
        }
    }

    // ---- write partials [blk][b][k][o] ----
#pragma unroll
    for (int kk = 0; kk < 2; kk++) {
        float* pp = g_part + ((size_t)blockIdx.x * 64 + b) * 256 + (size_t)(2 * kp + kk) * 16;
#pragma unroll
        for (int j = 0; j < 4; j++) {
            float2 v0 = unpack2(acc[kk][2 * j]);
            float2 v1 = unpack2(acc[kk][2 * j + 1]);
            *(float4*)(pp + 4 * j) = make_float4(v0.x, v0.y, v1.x, v1.y);
        }
    }
}

// Reduce NBLK partials, squash, update route / emit output.
// grid 64 (b), block 1024: q = tid>>8 (4-way split), t = tid&255 = k*16+o.
__global__ void __launch_bounds__(1024) squash_kernel(float scale, int mode,
                                                      float* __restrict__ out) {
    __shared__ float red[4][256];
    const int tid = threadIdx.x, q = tid >> 8, t = tid & 255;
    const int b = blockIdx.x;
    float s = 0.f;
#pragma unroll 4
    for (int j = q; j < NBLK; j += 4)
        s += g_part[((size_t)j * 64 + b) * 256 + t];
    red[q][t] = s;
    __syncthreads();
    if (tid < 256) {
        s = (red[0][t] + red[1][t]) + (red[2][t] + red[3][t]);
        s *= scale;
        float s2 = s * s;
        s2 += __shfl_xor_sync(0xffffffffu, s2, 1);
        s2 += __shfl_xor_sync(0xffffffffu, s2, 2);
        s2 += __shfl_xor_sync(0xffffffffu, s2, 4);
        s2 += __shfl_xor_sync(0xffffffffu, s2, 8);
        float sc = s2 / ((1.0f + s2) * sqrtf(s2));
        float v = sc * s;
        int idx = b * 256 + t;
        if (mode == 0)      g_route[idx] = v;    // route = out0
        else if (mode == 1) g_route[idx] += v;   // route = out0 + out1
        else                out[idx] = v;        // final [B,16,16]
    }
}

extern "C" void kernel_launch(void* const* d_in, const int* in_sizes, int n_in,
                              void* d_out, int out_size) {
    const float* x = (const float*)d_in[0];   // [64, 2048, 8]
    const float* W = (const float*)d_in[1];   // [2048, 16, 8, 16]
    float* out = (float*)d_out;               // [64, 16, 16]
    (void)in_sizes; (void)n_in; (void)out_size;

    noop_kernel<<<1, 1>>>();                              // profiler alignment
    pass_kernel<true ><<<NBLK, 512>>>(x, W);              // s0 partials
    squash_kernel<<<64, 1024>>>(1.0f / 16.0f, 0, out);    // out0 -> route
    pass_kernel<false><<<NBLK, 512>>>(x, W);              // 4th launch (profiled)
    squash_kernel<<<64, 1024>>>(1.0f, 1, out);            // route += out1
    pass_kernel<false><<<NBLK, 512>>>(x, W);              // s2 partials
    squash_kernel<<<64, 1024>>>(1.0f, 2, out);            // final output
}

// round 7
// speedup vs baseline: 1.7726x; 1.7168x over previous
#include <cuda_runtime.h>

// CapsuleBlock: B=64, N=2048, D_in=8, K=16, O=16, 3 routing iters.
// R7: crossbar-traffic fix. Thread = (4b, 2k, oq): every W float4 from smem
// feeds 4 b (register reuse) -> 16 LDS.128/thread/n (was 64). x read as
// full-warp broadcast LDS.128 per d. W smem layout = coalesced 512B blocks.
// Softmax: xor1,2 (bias over oq) + xor4,8,16 (over kp).

#define NBLK  148
#define CHUNK 14           // 148*14 = 2072 >= 2048

__device__ float g_part[(size_t)NBLK * 16384];   // partials [blk][b][k][o]
__device__ float g_route[16384];                 // routing vector [b][k][o]

typedef unsigned long long ull;

__device__ __forceinline__ ull pack2(float v) {
    ull r; asm("mov.b64 %0, {%1, %1};" : "=l"(r) : "f"(v)); return r;
}
__device__ __forceinline__ ull fma2(ull a, ull b, ull c) {
    ull d; asm("fma.rn.f32x2 %0, %1, %2, %3;" : "=l"(d) : "l"(a), "l"(b), "l"(c)); return d;
}
__device__ __forceinline__ ull mul2(ull a, ull b) {
    ull d; asm("mul.rn.f32x2 %0, %1, %2;" : "=l"(d) : "l"(a), "l"(b)); return d;
}
__device__ __forceinline__ float2 unpack2(ull v) {
    float2 r; asm("mov.b64 {%0, %1}, %2;" : "=f"(r.x), "=f"(r.y) : "l"(v)); return r;
}

__global__ void noop_kernel() {}

// pass: per n, h[b,k,o] = sum_d x[b,n,d] W[n,k,d,o].
// FIRST: acc += h. else: bias_k = <h,route>, softmax over k, acc += c_k h.
// 512 thr: warp w owns b = 4w..4w+3. lane l: oq = l&3, kp = (l>>2)&7.
// thread owns j=0..3 (b=4w+j), k = 2kp+kk, o = oq*4..oq*4+3.
template <bool FIRST>
__global__ void __launch_bounds__(512, 1)
pass_kernel(const float* __restrict__ x, const float* __restrict__ W) {
    // W tile: float4 index (d*2+kk)*32 + lane  -> compute LDS is a coalesced
    // 512B block (4 conflict-free phases). 8 KB.
    __shared__ __align__(16) float4 Wsf4[512];
    __shared__ __align__(16) float xs[CHUNK][8][64];     // [ln][d][b], 28 KB

    const int tid = threadIdx.x;
    const int l   = tid & 31;
    const int w   = tid >> 5;          // warp id = b-group
    const int n0  = blockIdx.x * CHUNK;
    int nmax = 2048 - n0; if (nmax > CHUNK) nmax = CHUNK; if (nmax < 0) nmax = 0;

    // ---- stage x chunk as [ln][d][b] (one-time) ----
    for (int i = tid; i < nmax * 128; i += 512) {
        int ln = i >> 7, r = i & 127, bb = r >> 1, dq = r & 1;
        float4 v = *(const float4*)(x + ((size_t)bb * 2048 + (size_t)(n0 + ln)) * 8 + dq * 4);
        xs[ln][dq * 4 + 0][bb] = v.x;
        xs[ln][dq * 4 + 1][bb] = v.y;
        xs[ln][dq * 4 + 2][bb] = v.z;
        xs[ln][dq * 4 + 3][bb] = v.w;
    }

    // ---- W staging: thread t stages gmem float4 #t of W[n] ----
    const int kW = tid >> 5, dW = (tid >> 2) & 7, oqW = tid & 3;
    const int wdst = (dW * 2 + (kW & 1)) * 32 + (kW >> 1) * 4 + oqW;
    const float4* wsrc = (const float4*)(W + (size_t)n0 * 2048) + tid;
    float4 wreg = make_float4(0.f, 0.f, 0.f, 0.f);
    if (nmax > 0) wreg = wsrc[0];

    ull acc[4][2][2];                  // [j][kk][u]
#pragma unroll
    for (int j = 0; j < 4; j++)
#pragma unroll
        for (int kk = 0; kk < 2; kk++) { acc[j][kk][0] = 0ull; acc[j][kk][1] = 0ull; }

    // routing vectors for this thread's outputs (persistent in regs)
    ull rr[4][2][2];
    if (!FIRST) {
        const int kp = (l >> 2) & 7, oq = l & 3;
#pragma unroll
        for (int j = 0; j < 4; j++)
#pragma unroll
            for (int kk = 0; kk < 2; kk++) {
                const ull* rp = (const ull*)(g_route + ((size_t)(4 * w + j) * 16 + 2 * kp + kk) * 16 + oq * 4);
                rr[j][kk][0] = rp[0];
                rr[j][kk][1] = rp[1];
            }
    }

    for (int ln = 0; ln < nmax; ln++) {
        Wsf4[wdst] = wreg;
        __syncthreads();
        if (ln + 1 < nmax) wreg = wsrc[(size_t)(ln + 1) * 512];

        ull h[4][2][2];
#pragma unroll
        for (int d = 0; d < 8; d++) {
            // full-warp broadcast: warp's 4 b of x for this d
            float4 xq = *(const float4*)&xs[ln][d][4 * w];
            ull xd[4];
            xd[0] = pack2(xq.x); xd[1] = pack2(xq.y);
            xd[2] = pack2(xq.z); xd[3] = pack2(xq.w);
#pragma unroll
            for (int kk = 0; kk < 2; kk++) {
                ulonglong2 wv = *(const ulonglong2*)&Wsf4[(d * 2 + kk) * 32 + l];
#pragma unroll
                for (int j = 0; j < 4; j++) {
                    if (FIRST) {
                        acc[j][kk][0] = fma2(xd[j], wv.x, acc[j][kk][0]);
                        acc[j][kk][1] = fma2(xd[j], wv.y, acc[j][kk][1]);
                    } else if (d == 0) {
                        h[j][kk][0] = mul2(xd[j], wv.x);
                        h[j][kk][1] = mul2(xd[j], wv.y);
                    } else {
                        h[j][kk][0] = fma2(xd[j], wv.x, h[j][kk][0]);
                        h[j][kk][1] = fma2(xd[j], wv.y, h[j][kk][1]);
                    }
                }
            }
        }
        __syncthreads();   // Ws reads done before next staging store

        if (!FIRST) {
            // bias partials over this thread's 4 o, completed over oq (xor 1,2)
            float bias[4][2];
#pragma unroll
            for (int j = 0; j < 4; j++)
#pragma unroll
                for (int kk = 0; kk < 2; kk++) {
                    ull t = mul2(h[j][kk][0], rr[j][kk][0]);
                    t = fma2(h[j][kk][1], rr[j][kk][1], t);
                    float2 q = unpack2(t);
                    float pb = q.x + q.y;
                    pb += __shfl_xor_sync(0xffffffffu, pb, 1);
                    pb += __shfl_xor_sync(0xffffffffu, pb, 2);
                    bias[j][kk] = pb;
                }
            // softmax over 16 k: local pair + xor 4,8,16 over kp lanes
#pragma unroll
            for (int j = 0; j < 4; j++) {
                float m = fmaxf(bias[j][0], bias[j][1]);
                m = fmaxf(m, __shfl_xor_sync(0xffffffffu, m, 4));
                m = fmaxf(m, __shfl_xor_sync(0xffffffffu, m, 8));
                m = fmaxf(m, __shfl_xor_sync(0xffffffffu, m, 16));
                float e0 = __expf(bias[j][0] - m);
                float e1 = __expf(bias[j][1] - m);
                float s = e0 + e1;
                s += __shfl_xor_sync(0xffffffffu, s, 4);
                s += __shfl_xor_sync(0xffffffffu, s, 8);
                s += __shfl_xor_sync(0xffffffffu, s, 16);
                float inv = __fdividef(1.0f, s);
                ull c0 = pack2(e0 * inv), c1 = pack2(e1 * inv);
                acc[j][0][0] = fma2(c0, h[j][0][0], acc[j][0][0]);
                acc[j][0][1] = fma2(c0, h[j][0][1], acc[j][0][1]);
                acc[j][1][0] = fma2(c1, h[j][1][0], acc[j][1][0]);
                acc[j][1][1] = fma2(c1, h[j][1][1], acc[j][1][1]);
            }
        }
    }

    // ---- write partials [blk][b][k][o] ----
    const int kp = (l >> 2) & 7, oq = l & 3;
#pragma unroll
    for (int j = 0; j < 4; j++)
#pragma unroll
        for (int kk = 0; kk < 2; kk++) {
            float* pp = g_part + ((size_t)blockIdx.x * 64 + (size_t)(4 * w + j)) * 256
                        + (size_t)(2 * kp + kk) * 16 + oq * 4;
            float2 v0 = unpack2(acc[j][kk][0]);
            float2 v1 = unpack2(acc[j][kk][1]);
            *(float4*)pp = make_float4(v0.x, v0.y, v1.x, v1.y);
        }
}

// Reduce NBLK partials, squash, update route / emit output.
// grid 64 (b), block 1024: q = tid>>8 (4-way split), t = tid&255 = k*16+o.
__global__ void __launch_bounds__(1024) squash_kernel(float scale, int mode,
                                                      float* __restrict__ out) {
    __shared__ float red[4][256];
    const int tid = threadIdx.x, q = tid >> 8, t = tid & 255;
    const int b = blockIdx.x;
    float s = 0.f;
#pragma unroll 4
    for (int j = q; j < NBLK; j += 4)
        s += g_part[((size_t)j * 64 + b) * 256 + t];
    red[q][t] = s;
    __syncthreads();
    if (tid < 256) {
        s = (red[0][t] + red[1][t]) + (red[2][t] + red[3][t]);
        s *= scale;
        float s2 = s * s;
        s2 += __shfl_xor_sync(0xffffffffu, s2, 1);
        s2 += __shfl_xor_sync(0xffffffffu, s2, 2);
        s2 += __shfl_xor_sync(0xffffffffu, s2, 4);
        s2 += __shfl_xor_sync(0xffffffffu, s2, 8);
        float sc = s2 / ((1.0f + s2) * sqrtf(s2));
        float v = sc * s;
        int idx = b * 256 + t;
        if (mode == 0)      g_route[idx] = v;    // route = out0
        else if (mode == 1) g_route[idx] += v;   // route = out0 + out1
        else                out[idx] = v;        // final [B,16,16]
    }
}

extern "C" void kernel_launch(void* const* d_in, const int* in_sizes, int n_in,
                              void* d_out, int out_size) {
    const float* x = (const float*)d_in[0];   // [64, 2048, 8]
    const float* W = (const float*)d_in[1];   // [2048, 16, 8, 16]
    float* out = (float*)d_out;               // [64, 16, 16]
    (void)in_sizes; (void)n_in; (void)out_size;

    noop_kernel<<<1, 1>>>();                              // profiler alignment
    pass_kernel<true ><<<NBLK, 512>>>(x, W);              // s0 partials
    squash_kernel<<<64, 1024>>>(1.0f / 16.0f, 0, out);    // out0 -> route
    pass_kernel<false><<<NBLK, 512>>>(x, W);              // 4th launch (profiled)
    squash_kernel<<<64, 1024>>>(1.0f, 1, out);            // route += out1
    pass_kernel<false><<<NBLK, 512>>>(x, W);              // s2 partials
    squash_kernel<<<64, 1024>>>(1.0f, 2, out);            // final output
}